// round 16
// baseline (speedup 1.0000x reference)
#include <cuda_runtime.h>
#include <cuda_bf16.h>
#include <cstdint>

#define NN 50000
#define NE 800000
#define CDIM 128
#define DIN 32
#define TT0 25000
#define NOUT 16

__device__ __forceinline__ uint32_t smem_to_u32(const void* p) {
    uint32_t a;
    asm("{ .reg .u64 t; cvta.to.shared.u64 t, %1; cvt.u32.u64 %0, t; }" : "=r"(a) : "l"(p));
    return a;
}

// ldmatrix x4 (portable since sm_75)
#define LDMX4(r, addr) \
    asm volatile("ldmatrix.sync.aligned.m8n8.x4.shared.b16 {%0,%1,%2,%3}, [%4];" \
                 : "=r"((r)[0]), "=r"((r)[1]), "=r"((r)[2]), "=r"((r)[3]) : "r"(addr))

// bf16 tensor-core mma (portable since sm_80)
#define MMA16816(d, a, b0_, b1_) \
    asm volatile("mma.sync.aligned.m16n8k16.row.col.f32.bf16.bf16.f32 " \
                 "{%0,%1,%2,%3}, {%4,%5,%6,%7}, {%8,%9}, {%0,%1,%2,%3};" \
                 : "+f"((d)[0]), "+f"((d)[1]), "+f"((d)[2]), "+f"((d)[3]) \
                 : "r"((a)[0]), "r"((a)[1]), "r"((a)[2]), "r"((a)[3]), \
                   "r"(b0_), "r"(b1_))

// ---- scratch (static device globals; no allocation allowed) ----
__device__ __nv_bfloat16 g_xhi[NN * CDIM];    // x0 hi (encode), then x1 hi (agg1)
__device__ __nv_bfloat16 g_xlo[NN * CDIM];    // x0 lo, then x1 lo
__device__ float g_U[NN * CDIM];              // layer-1 self half (fp32)
__device__ __nv_bfloat16 g_Un[NN * CDIM];     // layer-1 neigh half (bf16)
__device__ float g_V[NN * 32];                // folded layer-2 output
__device__ float g_bc[NOUT];                  // folded bias
__device__ __nv_bfloat16 g_BThi[256 * 128];   // W1^T [n][k] bf16 hi
__device__ __nv_bfloat16 g_BTlo[256 * 128];   // W1^T [n][k] bf16 lo
__device__ __nv_bfloat16 g_WcThi[32 * 128];   // Wc^T [n][k] bf16 hi (folded)
__device__ __nv_bfloat16 g_WcTlo[32 * 128];   // Wc^T [n][k] bf16 lo
__device__ int   g_cnt[NN];
__device__ int   g_bsum[256];
__device__ int   g_fill[NN];
__device__ int   g_ptr[NN + 1];
__device__ int   g_src[NE];

// ---------------------------------------------------------------
// stitched: fold | hist | encode | Bprep  (all independent)
#define NB_FOLD 17
#define NB_HIST 782
#define NB_ENC  592
#define NB_PREP 32
#define NB_STITCH (NB_FOLD + NB_HIST + NB_ENC + NB_PREP)

__global__ __launch_bounds__(256) void stitched_kernel(
    const float* __restrict__ f0, const float* __restrict__ f1,
    const float* __restrict__ w0, const float* __restrict__ b0v,
    const float* __restrict__ w1, const float* __restrict__ b1v,
    const int* __restrict__ row_idx,
    const int* __restrict__ ei,
    const float* __restrict__ ws0, const float* __restrict__ wn0,
    const float* __restrict__ ws1, const float* __restrict__ wn1,
    const float* __restrict__ b1L,
    const float* __restrict__ hw, const float* __restrict__ hb)
{
    __shared__ float sbuf[2 * DIN * CDIM + 2 * CDIM];
    int tid = threadIdx.x;
    int b = blockIdx.x;

    if (b < NB_FOLD) {
        // fold: Wc^T = ([Ws1|Wn1] @ Hw)^T, split bf16 hi/lo; bc = b1@Hw + Hb
        float* sH = sbuf;
        for (int i = tid; i < CDIM * NOUT; i += 256) sH[i] = hw[i];
        __syncthreads();
        if (b < 16) {
            int idx = b * 256 + tid;
            int half = (idx >> 4) & 1;
            int k = idx >> 5;
            int j = idx & 15;
            const float* W = half ? wn1 : ws1;
            float acc = 0.f;
            #pragma unroll 8
            for (int c = 0; c < CDIM; c++)
                acc += W[k * CDIM + c] * sH[c * NOUT + j];
            __nv_bfloat16 h = __float2bfloat16(acc);
            __nv_bfloat16 l = __float2bfloat16(acc - __bfloat162float(h));
            int n = half * 16 + j;
            g_WcThi[n * 128 + k] = h;
            g_WcTlo[n * 128 + k] = l;
        } else if (tid < NOUT) {
            float acc = hb[tid];
            for (int c = 0; c < CDIM; c++)
                acc += b1L[c] * sH[c * NOUT + tid];
            g_bc[tid] = acc;
        }
        return;
    }
    if (b < NB_FOLD + NB_HIST) {
        int i = (b - NB_FOLD) * 256 + tid;
        if (i < NE / 4) {
            int4 d = reinterpret_cast<const int4*>(ei + NE)[i];
            atomicAdd(&g_cnt[d.x], 1);
            atomicAdd(&g_cnt[d.y], 1);
            atomicAdd(&g_cnt[d.z], 1);
            atomicAdd(&g_cnt[d.w], 1);
        }
        return;
    }
    if (b < NB_FOLD + NB_HIST + NB_ENC) {
        float* sW0 = sbuf;
        float* sW1 = sbuf + DIN * CDIM;
        float* sb0 = sbuf + 2 * DIN * CDIM;
        float* sb1 = sb0 + CDIM;
        for (int i = tid; i < DIN * CDIM; i += 256) { sW0[i] = w0[i]; sW1[i] = w1[i]; }
        if (tid < CDIM) sb0[tid] = b0v[tid];
        else            sb1[tid - CDIM] = b1v[tid - CDIM];
        __syncthreads();

        int eb = b - (NB_FOLD + NB_HIST);
        int sub = tid >> 7;
        int ch = tid & 127;
        for (int n = eb * 2 + sub; n < NN; n += 2 * NB_ENC) {
            int r = row_idx[n];
            const float* f;
            const float* sW;
            float acc;
            if (r < TT0) { f = f0 + (size_t)r * DIN;          sW = sW0; acc = sb0[ch]; }
            else         { f = f1 + (size_t)(r - TT0) * DIN;  sW = sW1; acc = sb1[ch]; }
            #pragma unroll
            for (int k = 0; k < DIN; k++)
                acc += f[k] * sW[k * CDIM + ch];
            __nv_bfloat16 h = __float2bfloat16(acc);
            __nv_bfloat16 l = __float2bfloat16(acc - __bfloat162float(h));
            g_xhi[(size_t)n * CDIM + ch] = h;
            g_xlo[(size_t)n * CDIM + ch] = l;
        }
        return;
    }
    // ---- B prep: W^T[n][k] bf16 hi/lo ----
    {
        int base = (b - (NB_FOLD + NB_HIST + NB_ENC)) * 256 + tid;
        for (int idx = base; idx < 256 * 128; idx += NB_PREP * 256) {
            int n = idx >> 7;
            int k = idx & 127;
            float val = (n < 128) ? ws0[k * 128 + n] : wn0[k * 128 + (n - 128)];
            __nv_bfloat16 h = __float2bfloat16(val);
            __nv_bfloat16 l = __float2bfloat16(val - __bfloat162float(h));
            g_BThi[n * 128 + k] = h;
            g_BTlo[n * 128 + k] = l;
        }
    }
}

// ---------------------------------------------------------------
// two-pass parallel exclusive scan of g_cnt -> g_ptr, g_fill
#define SCAN_CH 196    // ceil(NN/256)

__global__ __launch_bounds__(256) void scan_sum_kernel() {
    int b = blockIdx.x;
    int t = threadIdx.x;
    int beg = b * SCAN_CH;
    int end = min(beg + SCAN_CH, NN);
    int s = 0;
    for (int i = beg + t; i < end; i += 256) s += g_cnt[i];
    __shared__ int red[256];
    red[t] = s;
    __syncthreads();
    #pragma unroll
    for (int o = 128; o > 0; o >>= 1) {
        if (t < o) red[t] += red[t + o];
        __syncthreads();
    }
    if (t == 0) g_bsum[b] = red[0];
}

__global__ __launch_bounds__(256) void scan_out_kernel() {
    int b = blockIdx.x;
    int t = threadIdx.x;
    __shared__ int ssum[256];
    ssum[t] = g_bsum[t];
    __syncthreads();
    #pragma unroll
    for (int o = 1; o < 256; o <<= 1) {
        int u = (t >= o) ? ssum[t - o] : 0;
        __syncthreads();
        ssum[t] += u;
        __syncthreads();
    }
    int blockoff = (b > 0) ? ssum[b - 1] : 0;
    int total = ssum[255];
    __syncthreads();
    int i = b * SCAN_CH + t;
    int c = (t < SCAN_CH && i < NN) ? g_cnt[i] : 0;
    ssum[t] = c;
    __syncthreads();
    #pragma unroll
    for (int o = 1; o < 256; o <<= 1) {
        int u = (t >= o) ? ssum[t - o] : 0;
        __syncthreads();
        ssum[t] += u;
        __syncthreads();
    }
    int excl = ssum[t] - c + blockoff;
    if (t < SCAN_CH && i < NN) { g_ptr[i] = excl; g_fill[i] = excl; }
    if (b == 255 && t == 255) g_ptr[NN] = total;
}

// ---------------------------------------------------------------
// fill: one edge per thread (max TLP, 1 independent atomic each)
__global__ void fill_kernel(const int* __restrict__ ei) {
    int e = blockIdx.x * blockDim.x + threadIdx.x;
    if (e < NE) {
        int s = ei[e];
        int d = ei[NE + e];
        int pos = atomicAdd(&g_fill[d], 1);
        g_src[pos] = s;
    }
}

// ---------------------------------------------------------------
// GEMM1 via mma.sync bf16 split precision: U = x0 @ [Ws | Wn]
// self (y=0): 3-term, fp32 out. neigh (y=1): 2-term, bf16 out.
// K staged in two 64-chunks, single-buffered: smem 64KB -> 2 CTAs/SM.
#define SMEM_HMMA 65536

__global__ __launch_bounds__(256, 2) void hmma1_kernel()
{
    extern __shared__ char smem[];
    uint32_t sbase = smem_to_u32(smem);
    int tid = threadIdx.x;
    int row0 = blockIdx.x * 128;
    bool neigh = (blockIdx.y != 0);

    int w = tid >> 5, lane = tid & 31;
    int mrow = (w >> 1) * 32;
    int ncol = (w & 1) * 64;

    float acc[2][8][4];
    #pragma unroll
    for (int mi = 0; mi < 2; mi++)
        #pragma unroll
        for (int nj = 0; nj < 8; nj++)
            #pragma unroll
            for (int q = 0; q < 4; q++) acc[mi][nj][q] = 0.f;

    const __nv_bfloat16* BH = g_BThi + (size_t)blockIdx.y * 128 * 128;
    const __nv_bfloat16* BL = g_BTlo + (size_t)blockIdx.y * 128 * 128;

    #pragma unroll 1
    for (int st = 0; st < 2; st++) {
        #pragma unroll
        for (int it = 0; it < 4; it++) {
            int i = tid + it * 256;
            int row = i >> 3, u = i & 7;
            uint32_t off = (uint32_t)row * 128 + (uint32_t)((u ^ (row & 7)) * 16);
            int gr = row0 + row;
            uint4 ah = make_uint4(0, 0, 0, 0), al = ah;
            if (gr < NN) {
                ah = *reinterpret_cast<const uint4*>(g_xhi + (size_t)gr * CDIM + st * 64 + u * 8);
                al = *reinterpret_cast<const uint4*>(g_xlo + (size_t)gr * CDIM + st * 64 + u * 8);
            }
            *reinterpret_cast<uint4*>(smem + off) = ah;
            *reinterpret_cast<uint4*>(smem + 16384 + off) = al;
            *reinterpret_cast<uint4*>(smem + 32768 + off) =
                *reinterpret_cast<const uint4*>(BH + (size_t)row * CDIM + st * 64 + u * 8);
            *reinterpret_cast<uint4*>(smem + 49152 + off) =
                *reinterpret_cast<const uint4*>(BL + (size_t)row * CDIM + st * 64 + u * 8);
        }
        __syncthreads();

        #pragma unroll
        for (int ksl = 0; ksl < 4; ksl++) {
            uint32_t ahf[2][4], alf[2][4];
            #pragma unroll
            for (int mi = 0; mi < 2; mi++) {
                int arow = mrow + mi * 16 + ((lane >> 3) & 1) * 8 + (lane & 7);
                int au = ksl * 2 + (lane >> 4);
                uint32_t ad = sbase + (uint32_t)arow * 128 + (uint32_t)((au ^ (arow & 7)) * 16);
                LDMX4(ahf[mi], ad);
                if (!neigh) LDMX4(alf[mi], ad + 16384);
            }
            #pragma unroll
            for (int nc = 0; nc < 4; nc++) {
                int brow = ncol + nc * 16 + (lane >> 4) * 8 + (lane & 7);
                int bu = ksl * 2 + ((lane >> 3) & 1);
                uint32_t bd = sbase + 32768 + (uint32_t)brow * 128 + (uint32_t)((bu ^ (brow & 7)) * 16);
                uint32_t bh[4], bl[4];
                LDMX4(bh, bd);
                LDMX4(bl, bd + 16384);
                #pragma unroll
                for (int mi = 0; mi < 2; mi++) {
                    MMA16816(acc[mi][2 * nc],     ahf[mi], bh[0], bh[1]);
                    MMA16816(acc[mi][2 * nc],     ahf[mi], bl[0], bl[1]);
                    MMA16816(acc[mi][2 * nc + 1], ahf[mi], bh[2], bh[3]);
                    MMA16816(acc[mi][2 * nc + 1], ahf[mi], bl[2], bl[3]);
                    if (!neigh) {
                        MMA16816(acc[mi][2 * nc],     alf[mi], bh[0], bh[1]);
                        MMA16816(acc[mi][2 * nc + 1], alf[mi], bh[2], bh[3]);
                    }
                }
            }
        }
        __syncthreads();
    }

    int lr = lane >> 2;
    int lc = (lane & 3) * 2;
    #pragma unroll
    for (int mi = 0; mi < 2; mi++) {
        #pragma unroll
        for (int nj = 0; nj < 8; nj++) {
            int col = ncol + nj * 8 + lc;
            int r0 = row0 + mrow + mi * 16 + lr;
            int r1 = r0 + 8;
            if (neigh) {
                if (r0 < NN) {
                    __nv_bfloat162 p = __floats2bfloat162_rn(acc[mi][nj][0], acc[mi][nj][1]);
                    *reinterpret_cast<__nv_bfloat162*>(g_Un + (size_t)r0 * CDIM + col) = p;
                }
                if (r1 < NN) {
                    __nv_bfloat162 p = __floats2bfloat162_rn(acc[mi][nj][2], acc[mi][nj][3]);
                    *reinterpret_cast<__nv_bfloat162*>(g_Un + (size_t)r1 * CDIM + col) = p;
                }
            } else {
                if (r0 < NN)
                    *reinterpret_cast<float2*>(g_U + (size_t)r0 * CDIM + col) =
                        make_float2(acc[mi][nj][0], acc[mi][nj][1]);
                if (r1 < NN)
                    *reinterpret_cast<float2*>(g_U + (size_t)r1 * CDIM + col) =
                        make_float2(acc[mi][nj][2], acc[mi][nj][3]);
            }
        }
    }
}

// ---------------------------------------------------------------
// agg1: x1[n] = relu(U_self[n] + mean_src Un[src] + b0), emitted bf16 hi/lo.
// Half-warp per edge row: 16 lanes x 16B (8 bf16) = 256B row; 2 edges per
// warp-iteration, 2x unroll -> 4 rows in flight. Cross-half shfl_xor(16).
__global__ __launch_bounds__(256) void agg1_kernel(const float* __restrict__ b0v)
{
    int w = (blockIdx.x * blockDim.x + threadIdx.x) >> 5;
    int lane = threadIdx.x & 31;
    if (w >= NN) return;
    int half = lane >> 4;       // which edge of the pair
    int hl = lane & 15;         // channel group: 8 channels at hl*8
    int beg = g_ptr[w], end = g_ptr[w + 1];

    float acc[8];
    #pragma unroll
    for (int i = 0; i < 8; i++) acc[i] = 0.f;

    const __nv_bfloat16* Un = g_Un + hl * 8;

    auto accum = [&](uint4 r) {
        __nv_bfloat162* p = reinterpret_cast<__nv_bfloat162*>(&r);
        #pragma unroll
        for (int q = 0; q < 4; q++) {
            float2 f = __bfloat1622float2(p[q]);
            acc[2 * q] += f.x;
            acc[2 * q + 1] += f.y;
        }
    };

    int e = beg;
    for (; e + 3 < end; e += 4) {
        int s0 = g_src[e + half];
        int s1 = g_src[e + 2 + half];
        uint4 r0 = *reinterpret_cast<const uint4*>(Un + (size_t)s0 * CDIM);
        uint4 r1 = *reinterpret_cast<const uint4*>(Un + (size_t)s1 * CDIM);
        accum(r0);
        accum(r1);
    }
    for (; e < end; e += 2) {
        if (e + half < end) {
            int s = g_src[e + half];
            uint4 r = *reinterpret_cast<const uint4*>(Un + (size_t)s * CDIM);
            accum(r);
        }
    }
    // combine the two half-warps
    #pragma unroll
    for (int i = 0; i < 8; i++)
        acc[i] += __shfl_xor_sync(0xffffffffu, acc[i], 16);

    float inv = 1.0f / fmaxf((float)(end - beg), 1.0f);
    int ch = hl * 8;
    float4 s0 = *reinterpret_cast<const float4*>(g_U + (size_t)w * CDIM + ch);
    float4 s1 = *reinterpret_cast<const float4*>(g_U + (size_t)w * CDIM + ch + 4);
    float4 bb0 = *reinterpret_cast<const float4*>(b0v + ch);
    float4 bb1 = *reinterpret_cast<const float4*>(b0v + ch + 4);
    float o[8];
    o[0] = fmaxf(s0.x + acc[0] * inv + bb0.x, 0.f);
    o[1] = fmaxf(s0.y + acc[1] * inv + bb0.y, 0.f);
    o[2] = fmaxf(s0.z + acc[2] * inv + bb0.z, 0.f);
    o[3] = fmaxf(s0.w + acc[3] * inv + bb0.w, 0.f);
    o[4] = fmaxf(s1.x + acc[4] * inv + bb1.x, 0.f);
    o[5] = fmaxf(s1.y + acc[5] * inv + bb1.y, 0.f);
    o[6] = fmaxf(s1.z + acc[6] * inv + bb1.z, 0.f);
    o[7] = fmaxf(s1.w + acc[7] * inv + bb1.w, 0.f);

    __nv_bfloat16 h[8];
    #pragma unroll
    for (int i = 0; i < 8; i++) h[i] = __float2bfloat16(o[i]);

    if (half == 0) {
        uint4 hv;
        __nv_bfloat162 p0; p0.x = h[0]; p0.y = h[1];
        __nv_bfloat162 p1; p1.x = h[2]; p1.y = h[3];
        __nv_bfloat162 p2; p2.x = h[4]; p2.y = h[5];
        __nv_bfloat162 p3; p3.x = h[6]; p3.y = h[7];
        hv.x = *reinterpret_cast<uint32_t*>(&p0);
        hv.y = *reinterpret_cast<uint32_t*>(&p1);
        hv.z = *reinterpret_cast<uint32_t*>(&p2);
        hv.w = *reinterpret_cast<uint32_t*>(&p3);
        *reinterpret_cast<uint4*>(g_xhi + (size_t)w * CDIM + ch) = hv;
    } else {
        uint4 lv;
        __nv_bfloat162 p0 = __floats2bfloat162_rn(o[0] - __bfloat162float(h[0]),
                                                  o[1] - __bfloat162float(h[1]));
        __nv_bfloat162 p1 = __floats2bfloat162_rn(o[2] - __bfloat162float(h[2]),
                                                  o[3] - __bfloat162float(h[3]));
        __nv_bfloat162 p2 = __floats2bfloat162_rn(o[4] - __bfloat162float(h[4]),
                                                  o[5] - __bfloat162float(h[5]));
        __nv_bfloat162 p3 = __floats2bfloat162_rn(o[6] - __bfloat162float(h[6]),
                                                  o[7] - __bfloat162float(h[7]));
        lv.x = *reinterpret_cast<uint32_t*>(&p0);
        lv.y = *reinterpret_cast<uint32_t*>(&p1);
        lv.z = *reinterpret_cast<uint32_t*>(&p2);
        lv.w = *reinterpret_cast<uint32_t*>(&p3);
        *reinterpret_cast<uint4*>(g_xlo + (size_t)w * CDIM + ch) = lv;
    }
}

// ---------------------------------------------------------------
// hmma2: V = x1 @ Wc via mma.sync bf16 (3-term split)
// CTA tile M=128 x N=32, K in two 64-chunks.
#define SMEM_HMMA2 40960

__global__ __launch_bounds__(256, 2) void hmma2_kernel()
{
    extern __shared__ char smem[];
    uint32_t sbase = smem_to_u32(smem);
    int tid = threadIdx.x;
    int row0 = blockIdx.x * 128;

    int w = tid >> 5, lane = tid & 31;
    int mrow = w * 16;

    float acc[4][4];
    #pragma unroll
    for (int nj = 0; nj < 4; nj++)
        #pragma unroll
        for (int q = 0; q < 4; q++) acc[nj][q] = 0.f;

    #pragma unroll 1
    for (int st = 0; st < 2; st++) {
        #pragma unroll
        for (int it = 0; it < 4; it++) {
            int i = tid + it * 256;
            int row = i >> 3, u = i & 7;
            uint32_t off = (uint32_t)row * 128 + (uint32_t)((u ^ (row & 7)) * 16);
            int gr = row0 + row;
            uint4 ah = make_uint4(0, 0, 0, 0), al = ah;
            if (gr < NN) {
                ah = *reinterpret_cast<const uint4*>(g_xhi + (size_t)gr * CDIM + st * 64 + u * 8);
                al = *reinterpret_cast<const uint4*>(g_xlo + (size_t)gr * CDIM + st * 64 + u * 8);
            }
            *reinterpret_cast<uint4*>(smem + off) = ah;
            *reinterpret_cast<uint4*>(smem + 16384 + off) = al;
        }
        {
            int row = tid >> 3, u = tid & 7;
            uint32_t off = (uint32_t)row * 128 + (uint32_t)((u ^ (row & 7)) * 16);
            *reinterpret_cast<uint4*>(smem + 32768 + off) =
                *reinterpret_cast<const uint4*>(g_WcThi + (size_t)row * 128 + st * 64 + u * 8);
            *reinterpret_cast<uint4*>(smem + 36864 + off) =
                *reinterpret_cast<const uint4*>(g_WcTlo + (size_t)row * 128 + st * 64 + u * 8);
        }
        __syncthreads();

        #pragma unroll
        for (int ksl = 0; ksl < 4; ksl++) {
            uint32_t ahf[4], alf[4];
            int arow = mrow + ((lane >> 3) & 1) * 8 + (lane & 7);
            int au = ksl * 2 + (lane >> 4);
            uint32_t ad = sbase + (uint32_t)arow * 128 + (uint32_t)((au ^ (arow & 7)) * 16);
            LDMX4(ahf, ad);
            LDMX4(alf, ad + 16384);
            #pragma unroll
            for (int nc = 0; nc < 2; nc++) {
                int brow = nc * 16 + (lane >> 4) * 8 + (lane & 7);
                int bu = ksl * 2 + ((lane >> 3) & 1);
                uint32_t bd = sbase + 32768 + (uint32_t)brow * 128 + (uint32_t)((bu ^ (brow & 7)) * 16);
                uint32_t bh[4], bl[4];
                LDMX4(bh, bd);
                LDMX4(bl, bd + 4096);
                MMA16816(acc[2 * nc],     ahf, bh[0], bh[1]);
                MMA16816(acc[2 * nc],     ahf, bl[0], bl[1]);
                MMA16816(acc[2 * nc],     alf, bh[0], bh[1]);
                MMA16816(acc[2 * nc + 1], ahf, bh[2], bh[3]);
                MMA16816(acc[2 * nc + 1], ahf, bl[2], bl[3]);
                MMA16816(acc[2 * nc + 1], alf, bh[2], bh[3]);
            }
        }
        __syncthreads();
    }

    int lr = lane >> 2;
    int lc = (lane & 3) * 2;
    #pragma unroll
    for (int nj = 0; nj < 4; nj++) {
        int col = nj * 8 + lc;
        int r0 = row0 + mrow + lr;
        int r1 = r0 + 8;
        if (r0 < NN)
            *reinterpret_cast<float2*>(g_V + (size_t)r0 * 32 + col) =
                make_float2(acc[nj][0], acc[nj][1]);
        if (r1 < NN)
            *reinterpret_cast<float2*>(g_V + (size_t)r1 * 32 + col) =
                make_float2(acc[nj][2], acc[nj][3]);
    }
}

// ---------------------------------------------------------------
__global__ __launch_bounds__(256) void agg2_kernel(float* __restrict__ out)
{
    int w = (blockIdx.x * blockDim.x + threadIdx.x) >> 5;
    int lane = threadIdx.x & 31;
    int n = w * 2 + (lane >> 4);
    int j = lane & 15;
    if (n >= NN) return;
    int beg = g_ptr[n], end = g_ptr[n + 1];
    float a0 = 0.f, a1 = 0.f;
    const float* Vn = g_V + 16 + j;
    int e = beg;
    for (; e + 3 < end; e += 4) {
        int s0 = g_src[e], s1 = g_src[e + 1], s2 = g_src[e + 2], s3 = g_src[e + 3];
        float v0 = Vn[(size_t)s0 * 32];
        float v1 = Vn[(size_t)s1 * 32];
        float v2 = Vn[(size_t)s2 * 32];
        float v3 = Vn[(size_t)s3 * 32];
        a0 += v0 + v2;
        a1 += v1 + v3;
    }
    for (; e < end; e++) a0 += Vn[(size_t)g_src[e] * 32];
    float acc = a0 + a1;
    float inv = 1.0f / fmaxf((float)(end - beg), 1.0f);
    out[(size_t)n * NOUT + j] = g_V[(size_t)n * 32 + j] + acc * inv + g_bc[j];
}

// ---------------------------------------------------------------
extern "C" void kernel_launch(void* const* d_in, const int* in_sizes, int n_in,
                              void* d_out, int out_size)
{
    const float* feats0   = (const float*)d_in[0];
    const float* feats1   = (const float*)d_in[1];
    const float* enc_w0   = (const float*)d_in[2];
    const float* enc_b0   = (const float*)d_in[3];
    const float* enc_w1   = (const float*)d_in[4];
    const float* enc_b1   = (const float*)d_in[5];
    const float* w_self0  = (const float*)d_in[6];
    const float* w_neigh0 = (const float*)d_in[7];
    const float* b0       = (const float*)d_in[8];
    const float* w_self1  = (const float*)d_in[9];
    const float* w_neigh1 = (const float*)d_in[10];
    const float* b1       = (const float*)d_in[11];
    const float* head_w   = (const float*)d_in[12];
    const float* head_b   = (const float*)d_in[13];
    const int*   row_idx  = (const int*)d_in[14];
    const int*   edge_ix  = (const int*)d_in[15];
    float* out = (float*)d_out;

    int* gcnt; cudaGetSymbolAddress((void**)&gcnt, g_cnt);

    cudaFuncSetAttribute(hmma1_kernel,
                         cudaFuncAttributeMaxDynamicSharedMemorySize, SMEM_HMMA);
    cudaFuncSetAttribute(hmma2_kernel,
                         cudaFuncAttributeMaxDynamicSharedMemorySize, SMEM_HMMA2);

    cudaMemsetAsync(gcnt, 0, NN * sizeof(int));

    stitched_kernel<<<NB_STITCH, 256>>>(
        feats0, feats1, enc_w0, enc_b0, enc_w1, enc_b1, row_idx,
        edge_ix, w_self0, w_neigh0, w_self1, w_neigh1, b1, head_w, head_b);

    scan_sum_kernel<<<256, 256>>>();
    scan_out_kernel<<<256, 256>>>();

    // fill in the ncu capture slot
    fill_kernel<<<(NE + 255) / 256, 256>>>(edge_ix);

    dim3 g1((NN + 127) / 128, 2);
    hmma1_kernel<<<g1, 256, SMEM_HMMA>>>();

    agg1_kernel<<<(NN * 32 + 255) / 256, 256>>>(b0);
    hmma2_kernel<<<(NN + 127) / 128, 256, SMEM_HMMA2>>>();
    agg2_kernel<<<(NN * 16 + 255) / 256, 256>>>(out);
}

// round 17
// speedup vs baseline: 1.0621x; 1.0621x over previous
#include <cuda_runtime.h>
#include <cuda_bf16.h>
#include <cstdint>

#define NN 50000
#define NE 800000
#define CDIM 128
#define DIN 32
#define TT0 25000
#define NOUT 16

__device__ __forceinline__ uint32_t smem_to_u32(const void* p) {
    uint32_t a;
    asm("{ .reg .u64 t; cvta.to.shared.u64 t, %1; cvt.u32.u64 %0, t; }" : "=r"(a) : "l"(p));
    return a;
}

// ldmatrix x4 (portable since sm_75)
#define LDMX4(r, addr) \
    asm volatile("ldmatrix.sync.aligned.m8n8.x4.shared.b16 {%0,%1,%2,%3}, [%4];" \
                 : "=r"((r)[0]), "=r"((r)[1]), "=r"((r)[2]), "=r"((r)[3]) : "r"(addr))

// bf16 tensor-core mma (portable since sm_80)
#define MMA16816(d, a, b0_, b1_) \
    asm volatile("mma.sync.aligned.m16n8k16.row.col.f32.bf16.bf16.f32 " \
                 "{%0,%1,%2,%3}, {%4,%5,%6,%7}, {%8,%9}, {%0,%1,%2,%3};" \
                 : "+f"((d)[0]), "+f"((d)[1]), "+f"((d)[2]), "+f"((d)[3]) \
                 : "r"((a)[0]), "r"((a)[1]), "r"((a)[2]), "r"((a)[3]), \
                   "r"(b0_), "r"(b1_))

// ---- scratch (static device globals; no allocation allowed) ----
__device__ __nv_bfloat16 g_xhi[NN * CDIM];    // x0 hi (encode), then x1 hi (agg1)
__device__ __nv_bfloat16 g_xlo[NN * CDIM];    // x0 lo, then x1 lo
__device__ float g_U[NN * CDIM];              // layer-1 self half (fp32)
__device__ __nv_bfloat16 g_Un[NN * CDIM];     // layer-1 neigh half (bf16)
__device__ float g_V[NN * 32];                // folded layer-2 output
__device__ float g_bc[NOUT];                  // folded bias
__device__ __nv_bfloat16 g_BThi[256 * 128];   // W1^T [n][k] bf16 hi
__device__ __nv_bfloat16 g_BTlo[256 * 128];   // W1^T [n][k] bf16 lo
__device__ __nv_bfloat16 g_WcThi[32 * 128];   // Wc^T [n][k] bf16 hi (folded)
__device__ __nv_bfloat16 g_WcTlo[32 * 128];   // Wc^T [n][k] bf16 lo
__device__ int   g_cnt[NN];
__device__ int   g_bsum[256];
__device__ int   g_fill[NN];
__device__ int   g_ptr[NN + 1];
__device__ int   g_src[NE];

// ---------------------------------------------------------------
// stitched: fold | hist | encode | Bprep  (all independent)
#define NB_FOLD 17
#define NB_HIST 782
#define NB_ENC  592
#define NB_PREP 32
#define NB_STITCH (NB_FOLD + NB_HIST + NB_ENC + NB_PREP)

__global__ __launch_bounds__(256) void stitched_kernel(
    const float* __restrict__ f0, const float* __restrict__ f1,
    const float* __restrict__ w0, const float* __restrict__ b0v,
    const float* __restrict__ w1, const float* __restrict__ b1v,
    const int* __restrict__ row_idx,
    const int* __restrict__ ei,
    const float* __restrict__ ws0, const float* __restrict__ wn0,
    const float* __restrict__ ws1, const float* __restrict__ wn1,
    const float* __restrict__ b1L,
    const float* __restrict__ hw, const float* __restrict__ hb)
{
    __shared__ float sbuf[2 * DIN * CDIM + 2 * CDIM];
    int tid = threadIdx.x;
    int b = blockIdx.x;

    if (b < NB_FOLD) {
        // fold: Wc^T = ([Ws1|Wn1] @ Hw)^T, split bf16 hi/lo; bc = b1@Hw + Hb
        float* sH = sbuf;
        for (int i = tid; i < CDIM * NOUT; i += 256) sH[i] = hw[i];
        __syncthreads();
        if (b < 16) {
            int idx = b * 256 + tid;
            int half = (idx >> 4) & 1;
            int k = idx >> 5;
            int j = idx & 15;
            const float* W = half ? wn1 : ws1;
            float acc = 0.f;
            #pragma unroll 8
            for (int c = 0; c < CDIM; c++)
                acc += W[k * CDIM + c] * sH[c * NOUT + j];
            __nv_bfloat16 h = __float2bfloat16(acc);
            __nv_bfloat16 l = __float2bfloat16(acc - __bfloat162float(h));
            int n = half * 16 + j;
            g_WcThi[n * 128 + k] = h;
            g_WcTlo[n * 128 + k] = l;
        } else if (tid < NOUT) {
            float acc = hb[tid];
            for (int c = 0; c < CDIM; c++)
                acc += b1L[c] * sH[c * NOUT + tid];
            g_bc[tid] = acc;
        }
        return;
    }
    if (b < NB_FOLD + NB_HIST) {
        int i = (b - NB_FOLD) * 256 + tid;
        if (i < NE / 4) {
            int4 d = reinterpret_cast<const int4*>(ei + NE)[i];
            atomicAdd(&g_cnt[d.x], 1);
            atomicAdd(&g_cnt[d.y], 1);
            atomicAdd(&g_cnt[d.z], 1);
            atomicAdd(&g_cnt[d.w], 1);
        }
        return;
    }
    if (b < NB_FOLD + NB_HIST + NB_ENC) {
        float* sW0 = sbuf;
        float* sW1 = sbuf + DIN * CDIM;
        float* sb0 = sbuf + 2 * DIN * CDIM;
        float* sb1 = sb0 + CDIM;
        for (int i = tid; i < DIN * CDIM; i += 256) { sW0[i] = w0[i]; sW1[i] = w1[i]; }
        if (tid < CDIM) sb0[tid] = b0v[tid];
        else            sb1[tid - CDIM] = b1v[tid - CDIM];
        __syncthreads();

        int eb = b - (NB_FOLD + NB_HIST);
        int sub = tid >> 7;
        int ch = tid & 127;
        for (int n = eb * 2 + sub; n < NN; n += 2 * NB_ENC) {
            int r = row_idx[n];
            const float* f;
            const float* sW;
            float acc;
            if (r < TT0) { f = f0 + (size_t)r * DIN;          sW = sW0; acc = sb0[ch]; }
            else         { f = f1 + (size_t)(r - TT0) * DIN;  sW = sW1; acc = sb1[ch]; }
            #pragma unroll
            for (int k = 0; k < DIN; k++)
                acc += f[k] * sW[k * CDIM + ch];
            __nv_bfloat16 h = __float2bfloat16(acc);
            __nv_bfloat16 l = __float2bfloat16(acc - __bfloat162float(h));
            g_xhi[(size_t)n * CDIM + ch] = h;
            g_xlo[(size_t)n * CDIM + ch] = l;
        }
        return;
    }
    // ---- B prep: W^T[n][k] bf16 hi/lo ----
    {
        int base = (b - (NB_FOLD + NB_HIST + NB_ENC)) * 256 + tid;
        for (int idx = base; idx < 256 * 128; idx += NB_PREP * 256) {
            int n = idx >> 7;
            int k = idx & 127;
            float val = (n < 128) ? ws0[k * 128 + n] : wn0[k * 128 + (n - 128)];
            __nv_bfloat16 h = __float2bfloat16(val);
            __nv_bfloat16 l = __float2bfloat16(val - __bfloat162float(h));
            g_BThi[n * 128 + k] = h;
            g_BTlo[n * 128 + k] = l;
        }
    }
}

// ---------------------------------------------------------------
// two-pass parallel exclusive scan of g_cnt -> g_ptr, g_fill
#define SCAN_CH 196    // ceil(NN/256)

__global__ __launch_bounds__(256) void scan_sum_kernel() {
    int b = blockIdx.x;
    int t = threadIdx.x;
    int beg = b * SCAN_CH;
    int end = min(beg + SCAN_CH, NN);
    int s = 0;
    for (int i = beg + t; i < end; i += 256) s += g_cnt[i];
    __shared__ int red[256];
    red[t] = s;
    __syncthreads();
    #pragma unroll
    for (int o = 128; o > 0; o >>= 1) {
        if (t < o) red[t] += red[t + o];
        __syncthreads();
    }
    if (t == 0) g_bsum[b] = red[0];
}

__global__ __launch_bounds__(256) void scan_out_kernel() {
    int b = blockIdx.x;
    int t = threadIdx.x;
    __shared__ int ssum[256];
    ssum[t] = g_bsum[t];
    __syncthreads();
    #pragma unroll
    for (int o = 1; o < 256; o <<= 1) {
        int u = (t >= o) ? ssum[t - o] : 0;
        __syncthreads();
        ssum[t] += u;
        __syncthreads();
    }
    int blockoff = (b > 0) ? ssum[b - 1] : 0;
    int total = ssum[255];
    __syncthreads();
    int i = b * SCAN_CH + t;
    int c = (t < SCAN_CH && i < NN) ? g_cnt[i] : 0;
    ssum[t] = c;
    __syncthreads();
    #pragma unroll
    for (int o = 1; o < 256; o <<= 1) {
        int u = (t >= o) ? ssum[t - o] : 0;
        __syncthreads();
        ssum[t] += u;
        __syncthreads();
    }
    int excl = ssum[t] - c + blockoff;
    if (t < SCAN_CH && i < NN) { g_ptr[i] = excl; g_fill[i] = excl; }
    if (b == 255 && t == 255) g_ptr[NN] = total;
}

// ---------------------------------------------------------------
// fill: one edge per thread (max TLP, 1 independent atomic each)
__global__ void fill_kernel(const int* __restrict__ ei) {
    int e = blockIdx.x * blockDim.x + threadIdx.x;
    if (e < NE) {
        int s = ei[e];
        int d = ei[NE + e];
        int pos = atomicAdd(&g_fill[d], 1);
        g_src[pos] = s;
    }
}

// ---------------------------------------------------------------
// GEMM1 via mma.sync bf16 split precision: U = x0 @ [Ws | Wn]
// self (y=0): 3-term, fp32 out. neigh (y=1): 2-term, bf16 out.
// K staged in two 64-chunks, single-buffered: smem 64KB -> 2 CTAs/SM.
#define SMEM_HMMA 65536

__global__ __launch_bounds__(256, 2) void hmma1_kernel()
{
    extern __shared__ char smem[];
    uint32_t sbase = smem_to_u32(smem);
    int tid = threadIdx.x;
    int row0 = blockIdx.x * 128;
    bool neigh = (blockIdx.y != 0);

    int w = tid >> 5, lane = tid & 31;
    int mrow = (w >> 1) * 32;
    int ncol = (w & 1) * 64;

    float acc[2][8][4];
    #pragma unroll
    for (int mi = 0; mi < 2; mi++)
        #pragma unroll
        for (int nj = 0; nj < 8; nj++)
            #pragma unroll
            for (int q = 0; q < 4; q++) acc[mi][nj][q] = 0.f;

    const __nv_bfloat16* BH = g_BThi + (size_t)blockIdx.y * 128 * 128;
    const __nv_bfloat16* BL = g_BTlo + (size_t)blockIdx.y * 128 * 128;

    #pragma unroll 1
    for (int st = 0; st < 2; st++) {
        #pragma unroll
        for (int it = 0; it < 4; it++) {
            int i = tid + it * 256;
            int row = i >> 3, u = i & 7;
            uint32_t off = (uint32_t)row * 128 + (uint32_t)((u ^ (row & 7)) * 16);
            int gr = row0 + row;
            uint4 ah = make_uint4(0, 0, 0, 0), al = ah;
            if (gr < NN) {
                ah = *reinterpret_cast<const uint4*>(g_xhi + (size_t)gr * CDIM + st * 64 + u * 8);
                al = *reinterpret_cast<const uint4*>(g_xlo + (size_t)gr * CDIM + st * 64 + u * 8);
            }
            *reinterpret_cast<uint4*>(smem + off) = ah;
            *reinterpret_cast<uint4*>(smem + 16384 + off) = al;
            *reinterpret_cast<uint4*>(smem + 32768 + off) =
                *reinterpret_cast<const uint4*>(BH + (size_t)row * CDIM + st * 64 + u * 8);
            *reinterpret_cast<uint4*>(smem + 49152 + off) =
                *reinterpret_cast<const uint4*>(BL + (size_t)row * CDIM + st * 64 + u * 8);
        }
        __syncthreads();

        #pragma unroll
        for (int ksl = 0; ksl < 4; ksl++) {
            uint32_t ahf[2][4], alf[2][4];
            #pragma unroll
            for (int mi = 0; mi < 2; mi++) {
                int arow = mrow + mi * 16 + ((lane >> 3) & 1) * 8 + (lane & 7);
                int au = ksl * 2 + (lane >> 4);
                uint32_t ad = sbase + (uint32_t)arow * 128 + (uint32_t)((au ^ (arow & 7)) * 16);
                LDMX4(ahf[mi], ad);
                if (!neigh) LDMX4(alf[mi], ad + 16384);
            }
            #pragma unroll
            for (int nc = 0; nc < 4; nc++) {
                int brow = ncol + nc * 16 + (lane >> 4) * 8 + (lane & 7);
                int bu = ksl * 2 + ((lane >> 3) & 1);
                uint32_t bd = sbase + 32768 + (uint32_t)brow * 128 + (uint32_t)((bu ^ (brow & 7)) * 16);
                uint32_t bh[4], bl[4];
                LDMX4(bh, bd);
                LDMX4(bl, bd + 16384);
                #pragma unroll
                for (int mi = 0; mi < 2; mi++) {
                    MMA16816(acc[mi][2 * nc],     ahf[mi], bh[0], bh[1]);
                    MMA16816(acc[mi][2 * nc],     ahf[mi], bl[0], bl[1]);
                    MMA16816(acc[mi][2 * nc + 1], ahf[mi], bh[2], bh[3]);
                    MMA16816(acc[mi][2 * nc + 1], ahf[mi], bl[2], bl[3]);
                    if (!neigh) {
                        MMA16816(acc[mi][2 * nc],     alf[mi], bh[0], bh[1]);
                        MMA16816(acc[mi][2 * nc + 1], alf[mi], bh[2], bh[3]);
                    }
                }
            }
        }
        __syncthreads();
    }

    int lr = lane >> 2;
    int lc = (lane & 3) * 2;
    #pragma unroll
    for (int mi = 0; mi < 2; mi++) {
        #pragma unroll
        for (int nj = 0; nj < 8; nj++) {
            int col = ncol + nj * 8 + lc;
            int r0 = row0 + mrow + mi * 16 + lr;
            int r1 = r0 + 8;
            if (neigh) {
                if (r0 < NN) {
                    __nv_bfloat162 p = __floats2bfloat162_rn(acc[mi][nj][0], acc[mi][nj][1]);
                    *reinterpret_cast<__nv_bfloat162*>(g_Un + (size_t)r0 * CDIM + col) = p;
                }
                if (r1 < NN) {
                    __nv_bfloat162 p = __floats2bfloat162_rn(acc[mi][nj][2], acc[mi][nj][3]);
                    *reinterpret_cast<__nv_bfloat162*>(g_Un + (size_t)r1 * CDIM + col) = p;
                }
            } else {
                if (r0 < NN)
                    *reinterpret_cast<float2*>(g_U + (size_t)r0 * CDIM + col) =
                        make_float2(acc[mi][nj][0], acc[mi][nj][1]);
                if (r1 < NN)
                    *reinterpret_cast<float2*>(g_U + (size_t)r1 * CDIM + col) =
                        make_float2(acc[mi][nj][2], acc[mi][nj][3]);
            }
        }
    }
}

// ---------------------------------------------------------------
// agg1 (round-15 config): x1[n] = relu(U_self[n] + mean_src Un[src] + b0),
// warp per node, 8B/lane bf16 gather, 4-way unroll; emits bf16 hi/lo.
__global__ __launch_bounds__(256) void agg1_kernel(const float* __restrict__ b0v)
{
    int w = (blockIdx.x * blockDim.x + threadIdx.x) >> 5;
    int lane = threadIdx.x & 31;
    if (w >= NN) return;
    int beg = g_ptr[w], end = g_ptr[w + 1];
    float4 acc0 = make_float4(0.f, 0.f, 0.f, 0.f);
    float4 acc1 = make_float4(0.f, 0.f, 0.f, 0.f);
    const __nv_bfloat16* Un = g_Un + lane * 4;

    auto fetch = [&](int s) -> float4 {
        uint2 raw = *reinterpret_cast<const uint2*>(Un + (size_t)s * CDIM);
        __nv_bfloat162 p0 = *reinterpret_cast<__nv_bfloat162*>(&raw.x);
        __nv_bfloat162 p1 = *reinterpret_cast<__nv_bfloat162*>(&raw.y);
        float2 f0 = __bfloat1622float2(p0);
        float2 f1 = __bfloat1622float2(p1);
        return make_float4(f0.x, f0.y, f1.x, f1.y);
    };

    int e = beg;
    for (; e + 3 < end; e += 4) {
        int s0 = g_src[e], s1 = g_src[e + 1], s2 = g_src[e + 2], s3 = g_src[e + 3];
        float4 v0 = fetch(s0);
        float4 v1 = fetch(s1);
        float4 v2 = fetch(s2);
        float4 v3 = fetch(s3);
        acc0.x += v0.x; acc0.y += v0.y; acc0.z += v0.z; acc0.w += v0.w;
        acc1.x += v1.x; acc1.y += v1.y; acc1.z += v1.z; acc1.w += v1.w;
        acc0.x += v2.x; acc0.y += v2.y; acc0.z += v2.z; acc0.w += v2.w;
        acc1.x += v3.x; acc1.y += v3.y; acc1.z += v3.z; acc1.w += v3.w;
    }
    for (; e < end; e++) {
        float4 v = fetch(g_src[e]);
        acc0.x += v.x; acc0.y += v.y; acc0.z += v.z; acc0.w += v.w;
    }
    float4 acc = make_float4(acc0.x + acc1.x, acc0.y + acc1.y,
                             acc0.z + acc1.z, acc0.w + acc1.w);
    float inv = 1.0f / fmaxf((float)(end - beg), 1.0f);
    float4 self = *reinterpret_cast<const float4*>(g_U + (size_t)w * CDIM + lane * 4);
    float4 b = *reinterpret_cast<const float4*>(b0v + lane * 4);
    float o0 = fmaxf(self.x + acc.x * inv + b.x, 0.f);
    float o1 = fmaxf(self.y + acc.y * inv + b.y, 0.f);
    float o2 = fmaxf(self.z + acc.z * inv + b.z, 0.f);
    float o3 = fmaxf(self.w + acc.w * inv + b.w, 0.f);

    __nv_bfloat16 h0 = __float2bfloat16(o0), h1 = __float2bfloat16(o1);
    __nv_bfloat16 h2 = __float2bfloat16(o2), h3 = __float2bfloat16(o3);
    __nv_bfloat162 hp0; hp0.x = h0; hp0.y = h1;
    __nv_bfloat162 hp1; hp1.x = h2; hp1.y = h3;
    __nv_bfloat162 lp0 = __floats2bfloat162_rn(o0 - __bfloat162float(h0), o1 - __bfloat162float(h1));
    __nv_bfloat162 lp1 = __floats2bfloat162_rn(o2 - __bfloat162float(h2), o3 - __bfloat162float(h3));
    uint2 hv, lv;
    hv.x = *reinterpret_cast<uint32_t*>(&hp0); hv.y = *reinterpret_cast<uint32_t*>(&hp1);
    lv.x = *reinterpret_cast<uint32_t*>(&lp0); lv.y = *reinterpret_cast<uint32_t*>(&lp1);
    *reinterpret_cast<uint2*>(g_xhi + (size_t)w * CDIM + lane * 4) = hv;
    *reinterpret_cast<uint2*>(g_xlo + (size_t)w * CDIM + lane * 4) = lv;
}

// ---------------------------------------------------------------
// hmma2: V = x1 @ Wc via mma.sync bf16 (3-term split)
// CTA tile M=128 x N=32, K in two 64-chunks.
#define SMEM_HMMA2 40960

__global__ __launch_bounds__(256, 2) void hmma2_kernel()
{
    extern __shared__ char smem[];
    uint32_t sbase = smem_to_u32(smem);
    int tid = threadIdx.x;
    int row0 = blockIdx.x * 128;

    int w = tid >> 5, lane = tid & 31;
    int mrow = w * 16;

    float acc[4][4];
    #pragma unroll
    for (int nj = 0; nj < 4; nj++)
        #pragma unroll
        for (int q = 0; q < 4; q++) acc[nj][q] = 0.f;

    #pragma unroll 1
    for (int st = 0; st < 2; st++) {
        #pragma unroll
        for (int it = 0; it < 4; it++) {
            int i = tid + it * 256;
            int row = i >> 3, u = i & 7;
            uint32_t off = (uint32_t)row * 128 + (uint32_t)((u ^ (row & 7)) * 16);
            int gr = row0 + row;
            uint4 ah = make_uint4(0, 0, 0, 0), al = ah;
            if (gr < NN) {
                ah = *reinterpret_cast<const uint4*>(g_xhi + (size_t)gr * CDIM + st * 64 + u * 8);
                al = *reinterpret_cast<const uint4*>(g_xlo + (size_t)gr * CDIM + st * 64 + u * 8);
            }
            *reinterpret_cast<uint4*>(smem + off) = ah;
            *reinterpret_cast<uint4*>(smem + 16384 + off) = al;
        }
        {
            int row = tid >> 3, u = tid & 7;
            uint32_t off = (uint32_t)row * 128 + (uint32_t)((u ^ (row & 7)) * 16);
            *reinterpret_cast<uint4*>(smem + 32768 + off) =
                *reinterpret_cast<const uint4*>(g_WcThi + (size_t)row * 128 + st * 64 + u * 8);
            *reinterpret_cast<uint4*>(smem + 36864 + off) =
                *reinterpret_cast<const uint4*>(g_WcTlo + (size_t)row * 128 + st * 64 + u * 8);
        }
        __syncthreads();

        #pragma unroll
        for (int ksl = 0; ksl < 4; ksl++) {
            uint32_t ahf[4], alf[4];
            int arow = mrow + ((lane >> 3) & 1) * 8 + (lane & 7);
            int au = ksl * 2 + (lane >> 4);
            uint32_t ad = sbase + (uint32_t)arow * 128 + (uint32_t)((au ^ (arow & 7)) * 16);
            LDMX4(ahf, ad);
            LDMX4(alf, ad + 16384);
            #pragma unroll
            for (int nc = 0; nc < 2; nc++) {
                int brow = nc * 16 + (lane >> 4) * 8 + (lane & 7);
                int bu = ksl * 2 + ((lane >> 3) & 1);
                uint32_t bd = sbase + 32768 + (uint32_t)brow * 128 + (uint32_t)((bu ^ (brow & 7)) * 16);
                uint32_t bh[4], bl[4];
                LDMX4(bh, bd);
                LDMX4(bl, bd + 4096);
                MMA16816(acc[2 * nc],     ahf, bh[0], bh[1]);
                MMA16816(acc[2 * nc],     ahf, bl[0], bl[1]);
                MMA16816(acc[2 * nc],     alf, bh[0], bh[1]);
                MMA16816(acc[2 * nc + 1], ahf, bh[2], bh[3]);
                MMA16816(acc[2 * nc + 1], ahf, bl[2], bl[3]);
                MMA16816(acc[2 * nc + 1], alf, bh[2], bh[3]);
            }
        }
        __syncthreads();
    }

    int lr = lane >> 2;
    int lc = (lane & 3) * 2;
    #pragma unroll
    for (int nj = 0; nj < 4; nj++) {
        int col = nj * 8 + lc;
        int r0 = row0 + mrow + lr;
        int r1 = r0 + 8;
        if (r0 < NN)
            *reinterpret_cast<float2*>(g_V + (size_t)r0 * 32 + col) =
                make_float2(acc[nj][0], acc[nj][1]);
        if (r1 < NN)
            *reinterpret_cast<float2*>(g_V + (size_t)r1 * 32 + col) =
                make_float2(acc[nj][2], acc[nj][3]);
    }
}

// ---------------------------------------------------------------
__global__ __launch_bounds__(256) void agg2_kernel(float* __restrict__ out)
{
    int w = (blockIdx.x * blockDim.x + threadIdx.x) >> 5;
    int lane = threadIdx.x & 31;
    int n = w * 2 + (lane >> 4);
    int j = lane & 15;
    if (n >= NN) return;
    int beg = g_ptr[n], end = g_ptr[n + 1];
    float a0 = 0.f, a1 = 0.f;
    const float* Vn = g_V + 16 + j;
    int e = beg;
    for (; e + 3 < end; e += 4) {
        int s0 = g_src[e], s1 = g_src[e + 1], s2 = g_src[e + 2], s3 = g_src[e + 3];
        float v0 = Vn[(size_t)s0 * 32];
        float v1 = Vn[(size_t)s1 * 32];
        float v2 = Vn[(size_t)s2 * 32];
        float v3 = Vn[(size_t)s3 * 32];
        a0 += v0 + v2;
        a1 += v1 + v3;
    }
    for (; e < end; e++) a0 += Vn[(size_t)g_src[e] * 32];
    float acc = a0 + a1;
    float inv = 1.0f / fmaxf((float)(end - beg), 1.0f);
    out[(size_t)n * NOUT + j] = g_V[(size_t)n * 32 + j] + acc * inv + g_bc[j];
}

// ---------------------------------------------------------------
extern "C" void kernel_launch(void* const* d_in, const int* in_sizes, int n_in,
                              void* d_out, int out_size)
{
    const float* feats0   = (const float*)d_in[0];
    const float* feats1   = (const float*)d_in[1];
    const float* enc_w0   = (const float*)d_in[2];
    const float* enc_b0   = (const float*)d_in[3];
    const float* enc_w1   = (const float*)d_in[4];
    const float* enc_b1   = (const float*)d_in[5];
    const float* w_self0  = (const float*)d_in[6];
    const float* w_neigh0 = (const float*)d_in[7];
    const float* b0       = (const float*)d_in[8];
    const float* w_self1  = (const float*)d_in[9];
    const float* w_neigh1 = (const float*)d_in[10];
    const float* b1       = (const float*)d_in[11];
    const float* head_w   = (const float*)d_in[12];
    const float* head_b   = (const float*)d_in[13];
    const int*   row_idx  = (const int*)d_in[14];
    const int*   edge_ix  = (const int*)d_in[15];
    float* out = (float*)d_out;

    int* gcnt; cudaGetSymbolAddress((void**)&gcnt, g_cnt);

    // one-time host-side handles (no device memory)
    static cudaStream_t sCSR = nullptr;
    static cudaEvent_t evStitched = nullptr, evFill = nullptr;
    if (sCSR == nullptr) {
        cudaStreamCreateWithFlags(&sCSR, cudaStreamNonBlocking);
        cudaEventCreateWithFlags(&evStitched, cudaEventDisableTiming);
        cudaEventCreateWithFlags(&evFill, cudaEventDisableTiming);
        cudaFuncSetAttribute(hmma1_kernel,
                             cudaFuncAttributeMaxDynamicSharedMemorySize, SMEM_HMMA);
        cudaFuncSetAttribute(hmma2_kernel,
                             cudaFuncAttributeMaxDynamicSharedMemorySize, SMEM_HMMA2);
    }

    cudaMemsetAsync(gcnt, 0, NN * sizeof(int));

    stitched_kernel<<<NB_STITCH, 256>>>(
        feats0, feats1, enc_w0, enc_b0, enc_w1, enc_b1, row_idx,
        edge_ix, w_self0, w_neigh0, w_self1, w_neigh1, b1, head_w, head_b);
    cudaEventRecord(evStitched, 0);

    // CSR tail on side stream, concurrent with hmma1
    cudaStreamWaitEvent(sCSR, evStitched, 0);
    scan_sum_kernel<<<256, 256, 0, sCSR>>>();
    scan_out_kernel<<<256, 256, 0, sCSR>>>();
    fill_kernel<<<(NE + 255) / 256, 256, 0, sCSR>>>(edge_ix);
    cudaEventRecord(evFill, sCSR);

    // main stream: hmma1 needs only stitched outputs
    dim3 g1((NN + 127) / 128, 2);
    hmma1_kernel<<<g1, 256, SMEM_HMMA>>>();

    // join: agg1 needs CSR + hmma1
    cudaStreamWaitEvent(0, evFill, 0);
    agg1_kernel<<<(NN * 32 + 255) / 256, 256>>>(b0);
    hmma2_kernel<<<(NN + 127) / 128, 256, SMEM_HMMA2>>>();
    agg2_kernel<<<(NN * 16 + 255) / 256, 256>>>(out);
}